// round 9
// baseline (speedup 1.0000x reference)
#include <cuda_runtime.h>
#include <cuda_fp16.h>

// ---------------- problem constants ----------------
#define Bb   2
#define Ss   2048
#define DMm  256
#define DIi  512
#define NN   16
#define RR   32
#define MM   (Bb*Ss)          // 4096 rows per chain
#define M2   (2*MM)           // 8192 rows: [fwd | reversed]
#define CHUNK 32
#define NCH  (Ss/CHUNK)       // 64 chunks per sequence
#define NSEQ 4                // 4 sequences total (2 fwd + 2 rev)
#define KS   4                // split-K for x-proj

// ---------------- device scratch ----------------
__device__ float  g_res [M2*DMm];
__device__ __half g_xs  [M2*DIi];
__device__ __half g_z   [M2*DIi];
__device__ __half g_xc  [M2*DIi];
__device__ float  g_proj[M2*64];          // [xd(32) | B(16) | C(16)] fp32
__device__ __half g_projh[M2*64];         // half mirror for gemm_dt A-path
__device__ float  g_projp[KS*M2*64];      // split-K partials (fp32)
__device__ __half g_delta[M2*DIi];
__device__ __half g_yg  [M2*DIi];
__device__ float  g_P   [NSEQ*NCH*DIi*NN];
__device__ float  g_Q   [NSEQ*NCH*DIi*NN];
__device__ float  g_Hin [NSEQ*NCH*DIi*NN];

__device__ __forceinline__ float siluf(float x){ return x / (1.f + __expf(-x)); }
__device__ __forceinline__ float spf(float a){ return (a > 20.f) ? a : log1pf(__expf(a)); }

__device__ __forceinline__ unsigned h2pack(float a, float b){
  __half2 h = __floats2half2_rn(a, b);
  return *reinterpret_cast<unsigned*>(&h);
}
__device__ __forceinline__ float4 h4load(const __half* p){
  uint2 u = *(const uint2*)p;
  float2 fa = __half22float2(*(__half2*)&u.x);
  float2 fb = __half22float2(*(__half2*)&u.y);
  return make_float4(fa.x, fa.y, fb.x, fb.y);
}
__device__ __forceinline__ void h4store(__half* p, float4 v){
  uint2 u; u.x = h2pack(v.x, v.y); u.y = h2pack(v.z, v.w);
  *(uint2*)p = u;
}

#define MMA16(c, a, b)                                                       \
  asm volatile("mma.sync.aligned.m16n8k16.row.col.f32.f16.f16.f32 "          \
               "{%0,%1,%2,%3},{%4,%5,%6,%7},{%8,%9},{%0,%1,%2,%3};"          \
               : "+f"((c)[0]), "+f"((c)[1]), "+f"((c)[2]), "+f"((c)[3])      \
               : "r"((a)[0]), "r"((a)[1]), "r"((a)[2]), "r"((a)[3]),         \
                 "r"((b)[0]), "r"((b)[1]))

// ---------------- init: fwd + reversed copies ----------------
__global__ void k_init(const float* __restrict__ x){
  int idx = blockIdx.x*256 + threadIdx.x;       // M2*64 float4s
  int col = idx & 63;
  int m   = idx >> 6;                           // 0..8191
  int half = m >> 12;
  int b = (m >> 11) & 1, s = m & (Ss-1);
  int ms = b*Ss + (half ? (Ss-1-s) : s);
  reinterpret_cast<float4*>(g_res)[m*64+col] =
      reinterpret_cast<const float4*>(x)[ms*64+col];
}

// ======================================================================
// FP16 tensor-core GEMM core, double-buffered, mma.m16n8k16.
// Block tile 128(M) x 64(N), 256 threads = 8 warps (4 M x 2 N),
// warp tile 32x32. K-chunk = 32 = TWO mma k-steps per barrier.
// Smem fragment order:
//   Af[mt(8)][lane(32)][8 regs]  (regs 0-3 = k0-15, 4-7 = k16-31)
//   Bf[nt(8)][lane(32)][4 regs]  (regs 0-1 = k0-15, 2-3 = k16-31)
// A staging: thread t covers (row = t>>1, k-half = (t&1)*16).
// B staging: thread t covers (n = t&63, k-octet = (t>>6)*8).
// ======================================================================
#define TC_DECL()                                                     \
  __shared__ __align__(16) unsigned Af[2][2048];                      \
  __shared__ __align__(16) unsigned Bf[2][1024];                      \
  const int t = threadIdx.x;                                          \
  const int lane = t & 31, wid = t >> 5;                              \
  const int wm = wid >> 1, wn = wid & 1;                              \
  const int s_r  = t >> 1;          /* A staging row 0..127   */      \
  const int s_kh = (t & 1);         /* A staging k-half 0/1   */      \
  const int s_bq = t >> 6;          /* B staging k-octet 0..3 */      \
  const int s_bn = t & 63;          /* B staging n 0..63      */      \
  const int a_off = (((s_r>>4)*32 + (s_r&7)*4)*8) + ((s_r>>3)&1) + 4*s_kh; \
  const int b_off = (((s_bn>>3)*32 + (s_bn&7)*4)*4) + s_bq;           \
  float acc[2][4][4] = {};                                            \
  float4 raA0, raA1, raA2, raA3; uint4 raH0, raH1;                    \
  float rb0, rb1, rb2, rb3, rb4, rb5, rb6, rb7;                       \
  (void)raA0; (void)raA1; (void)raA2; (void)raA3;                     \
  (void)raH0; (void)raH1;

#define TC_STAGE_B(buf) {                                             \
  unsigned* bb = &Bf[buf][b_off];                                     \
  bb[0]  = h2pack(rb0, rb1);                                          \
  bb[4]  = h2pack(rb2, rb3);                                          \
  bb[8]  = h2pack(rb4, rb5);                                          \
  bb[12] = h2pack(rb6, rb7); }

#define TC_STAGE_F(buf) {                                             \
  unsigned* ab = &Af[buf][a_off];                                     \
  ab[0]  = h2pack(raA0.x, raA0.y);                                    \
  ab[8]  = h2pack(raA0.z, raA0.w);                                    \
  ab[16] = h2pack(raA1.x, raA1.y);                                    \
  ab[24] = h2pack(raA1.z, raA1.w);                                    \
  ab[2]  = h2pack(raA2.x, raA2.y);                                    \
  ab[10] = h2pack(raA2.z, raA2.w);                                    \
  ab[18] = h2pack(raA3.x, raA3.y);                                    \
  ab[26] = h2pack(raA3.z, raA3.w);                                    \
  TC_STAGE_B(buf) }

#define TC_STAGE_H(buf) {                                             \
  unsigned* ab = &Af[buf][a_off];                                     \
  ab[0]  = raH0.x;                                                    \
  ab[8]  = raH0.y;                                                    \
  ab[16] = raH0.z;                                                    \
  ab[24] = raH0.w;                                                    \
  ab[2]  = raH1.x;                                                    \
  ab[10] = raH1.y;                                                    \
  ab[18] = raH1.z;                                                    \
  ab[26] = raH1.w;                                                    \
  TC_STAGE_B(buf) }

// two mma k-steps per chunk; step-1 fragment loads issue after step-0 mma
// so compute-phase register peak matches the 16-k core.
#define TC_COMP(buf) {                                                \
  unsigned a_[2][4]; unsigned b_[4][2];                               \
  _Pragma("unroll") for (int mt=0;mt<2;mt++)                          \
    *(uint4*)a_[mt] = *(const uint4*)&Af[buf][((wm*2+mt)*32 + lane)*8]; \
  _Pragma("unroll") for (int nt=0;nt<4;nt++)                          \
    *(uint2*)b_[nt] = *(const uint2*)&Bf[buf][((wn*4+nt)*32 + lane)*4]; \
  _Pragma("unroll") for (int mt=0;mt<2;mt++)                          \
    _Pragma("unroll") for (int nt=0;nt<4;nt++)                        \
      MMA16(acc[mt][nt], a_[mt], b_[nt]);                             \
  _Pragma("unroll") for (int mt=0;mt<2;mt++)                          \
    *(uint4*)a_[mt] = *(const uint4*)&Af[buf][((wm*2+mt)*32 + lane)*8 + 4]; \
  _Pragma("unroll") for (int nt=0;nt<4;nt++)                          \
    *(uint2*)b_[nt] = *(const uint2*)&Bf[buf][((wn*4+nt)*32 + lane)*4 + 2]; \
  _Pragma("unroll") for (int mt=0;mt<2;mt++)                          \
    _Pragma("unroll") for (int nt=0;nt<4;nt++)                        \
      MMA16(acc[mt][nt], a_[mt], b_[nt]); }

#define TC_BODY_GEN(KT, STG)                                          \
  LOADA(0); LOADB(0);                                                 \
  STG(0);                                                             \
  if (32 < (KT)) { LOADA(32); LOADB(32); }                            \
  __syncthreads();                                                    \
  { int cur = 0;                                                      \
    _Pragma("unroll 1")                                               \
    for (int k0=0; k0<(KT); k0+=32){                                  \
      if (k0+32 < (KT)) STG(cur^1);                                   \
      if (k0+64 < (KT)) { LOADA(k0+64); LOADB(k0+64); }               \
      TC_COMP(cur);                                                   \
      __syncthreads();                                                \
      cur ^= 1;                                                       \
    } }

#define TC_BODY(KT)   TC_BODY_GEN(KT, TC_STAGE_F)
#define TC_BODY_H(KT) TC_BODY_GEN(KT, TC_STAGE_H)

// in_proj with fused LayerNorm:
//   LN(g_res)[8192,256] @ in_w[256,1024] -> xs | z (half)   per-half weights
__global__ void __launch_bounds__(256,3)
k_gemm_in(const float* __restrict__ W0, const float* __restrict__ W1,
          const float* __restrict__ g0, const float* __restrict__ bt0,
          const float* __restrict__ g1, const float* __restrict__ bt1){
  int col0 = blockIdx.x*64, row0 = blockIdx.y*128;
  int half = row0 >> 12;
  const float* W  = half ? W1  : W0;
  const float* gm = half ? g1  : g0;
  const float* bb = half ? bt1 : bt0;
  __shared__ float sG[DMm], sBt[DMm];
  TC_DECL();
  sG[t] = gm[t]; sBt[t] = bb[t];
  const float* rowp = g_res + (size_t)(row0 + s_r)*DMm;
  // per-row LN stats: 2 threads per row (k-halves), reduce over pair
  float sum = 0.f, sq = 0.f;
  #pragma unroll
  for (int j=0;j<8;j++){
    #pragma unroll
    for (int i=0;i<4;i++){
      float4 v = *(const float4*)&rowp[j*32 + s_kh*16 + i*4];
      sum += v.x+v.y+v.z+v.w;
      sq  += v.x*v.x+v.y*v.y+v.z*v.z+v.w*v.w;
    }
  }
  sum += __shfl_xor_sync(~0u, sum, 1);
  sq  += __shfl_xor_sync(~0u, sq, 1);
  float mean = sum*(1.f/DMm);
  float rstd = rsqrtf(sq*(1.f/DMm) - mean*mean + 1e-5f);
  __syncthreads();   // sG/sBt visible
#define LNV(v, kk)                                                     \
    v.x=(v.x-mean)*rstd*sG[(kk)+0]+sBt[(kk)+0];                        \
    v.y=(v.y-mean)*rstd*sG[(kk)+1]+sBt[(kk)+1];                        \
    v.z=(v.z-mean)*rstd*sG[(kk)+2]+sBt[(kk)+2];                        \
    v.w=(v.w-mean)*rstd*sG[(kk)+3]+sBt[(kk)+3];
#define LOADA(k0_) { int kk_=(k0_)+s_kh*16;                                        \
    raA0 = *(const float4*)&rowp[kk_];       LNV(raA0, kk_);                       \
    raA1 = *(const float4*)&rowp[kk_+4];     LNV(raA1, kk_+4);                     \
    raA2 = *(const float4*)&rowp[kk_+8];     LNV(raA2, kk_+8);                     \
    raA3 = *(const float4*)&rowp[kk_+12];    LNV(raA3, kk_+12); }
#define LOADB(k0_) { int kb_ = (k0_) + s_bq*8;                                     \
                     rb0 = W[(size_t)(kb_+0)*(2*DIi) + col0 + s_bn];               \
                     rb1 = W[(size_t)(kb_+1)*(2*DIi) + col0 + s_bn];               \
                     rb2 = W[(size_t)(kb_+2)*(2*DIi) + col0 + s_bn];               \
                     rb3 = W[(size_t)(kb_+3)*(2*DIi) + col0 + s_bn];               \
                     rb4 = W[(size_t)(kb_+4)*(2*DIi) + col0 + s_bn];               \
                     rb5 = W[(size_t)(kb_+5)*(2*DIi) + col0 + s_bn];               \
                     rb6 = W[(size_t)(kb_+6)*(2*DIi) + col0 + s_bn];               \
                     rb7 = W[(size_t)(kb_+7)*(2*DIi) + col0 + s_bn]; }
  TC_BODY(DMm);
#undef LOADA
#undef LOADB
#undef LNV
  __half* dst = (col0 < DIi) ? g_xs : g_z;
  int cb = (col0 < DIi) ? col0 : col0 - DIi;
  #pragma unroll
  for (int mt=0;mt<2;mt++)
    #pragma unroll
    for (int nt=0;nt<4;nt++){
      int r = row0 + wm*32 + mt*16 + (lane>>2);
      int c = cb + wn*32 + nt*8 + (lane&3)*2;
      *(unsigned*)&dst[(size_t)r*DIi + c]     = h2pack(acc[mt][nt][0], acc[mt][nt][1]);
      *(unsigned*)&dst[(size_t)(r+8)*DIi + c] = h2pack(acc[mt][nt][2], acc[mt][nt][3]);
    }
}

// x-proj split-K: xc[8192,512](half) @ [xd(32)|xB(16)|xC(16)] -> projp[kz] (fp32)
__global__ void __launch_bounds__(256,3)
k_gemm_x(const float* __restrict__ xdw0, const float* __restrict__ xbw0,
         const float* __restrict__ xcw0,
         const float* __restrict__ xdw1, const float* __restrict__ xbw1,
         const float* __restrict__ xcw1){
  int kz = blockIdx.x, row0 = blockIdx.y*128;
  int half = row0 >> 12;
  int kbase = kz*(DIi/KS);
  TC_DECL();
  const float* bsrc; int ldb, boff;
  if      (s_bn < 32){ bsrc = half?xdw1:xdw0; ldb = 32; boff = s_bn;      }
  else if (s_bn < 48){ bsrc = half?xbw1:xbw0; ldb = 16; boff = s_bn - 32; }
  else               { bsrc = half?xcw1:xcw0; ldb = 16; boff = s_bn - 48; }
#define LOADA(k0_) { const __half* ap = &g_xc[(size_t)(row0+s_r)*DIi + kbase+(k0_)+s_kh*16]; \
                     raH0 = *(const uint4*)ap; raH1 = *(const uint4*)(ap+8); }
#define LOADB(k0_) { int kb_ = kbase + (k0_) + s_bq*8;                                   \
                     rb0 = bsrc[(kb_+0)*ldb + boff];                                     \
                     rb1 = bsrc[(kb_+1)*ldb + boff];                                     \
                     rb2 = bsrc[(kb_+2)*ldb + boff];                                     \
                     rb3 = bsrc[(kb_+3)*ldb + boff];                                     \
                     rb4 = bsrc[(kb_+4)*ldb + boff];                                     \
                     rb5 = bsrc[(kb_+5)*ldb + boff];                                     \
                     rb6 = bsrc[(kb_+6)*ldb + boff];                                     \
                     rb7 = bsrc[(kb_+7)*ldb + boff]; }
  TC_BODY_H(DIi/KS);
#undef LOADA
#undef LOADB
  float* dst = g_projp + (size_t)kz*M2*64;
  #pragma unroll
  for (int mt=0;mt<2;mt++)
    #pragma unroll
    for (int nt=0;nt<4;nt++){
      int r = row0 + wm*32 + mt*16 + (lane>>2);
      int c = wn*32 + nt*8 + (lane&3)*2;
      *(float2*)&dst[(size_t)r*64 + c]     = make_float2(acc[mt][nt][0], acc[mt][nt][1]);
      *(float2*)&dst[(size_t)(r+8)*64 + c] = make_float2(acc[mt][nt][2], acc[mt][nt][3]);
    }
}

__global__ void k_xred(){
  int i = blockIdx.x*256 + threadIdx.x;   // M2*16 float4s
  float4 a = reinterpret_cast<const float4*>(g_projp)[i];
  float4 b = reinterpret_cast<const float4*>(g_projp + (size_t)M2*64)[i];
  float4 c = reinterpret_cast<const float4*>(g_projp + (size_t)2*M2*64)[i];
  float4 d = reinterpret_cast<const float4*>(g_projp + (size_t)3*M2*64)[i];
  float4 s = make_float4(a.x+b.x+c.x+d.x, a.y+b.y+c.y+d.y,
                         a.z+b.z+c.z+d.z, a.w+b.w+c.w+d.w);
  reinterpret_cast<float4*>(g_proj)[i] = s;
  h4store(&g_projh[i*4], s);
}

// delta: softplus(projh[:, :32] @ dtp_w[32,512] + dtp_b) -> g_delta (half)
__global__ void __launch_bounds__(256,3)
k_gemm_dt(const float* __restrict__ Wd0, const float* __restrict__ bd0,
          const float* __restrict__ Wd1, const float* __restrict__ bd1){
  int col0 = blockIdx.x*64, row0 = blockIdx.y*128;
  int half = row0 >> 12;
  const float* Wd = half ? Wd1 : Wd0;
  const float* bd = half ? bd1 : bd0;
  TC_DECL();
#define LOADA(k0_) { const __half* ap = &g_projh[(size_t)(row0+s_r)*64 + (k0_)+s_kh*16]; \
                     raH0 = *(const uint4*)ap; raH1 = *(const uint4*)(ap+8); }
#define LOADB(k0_) { int kb_ = (k0_) + s_bq*8;                                      \
                     rb0 = Wd[(kb_+0)*DIi + col0 + s_bn];                           \
                     rb1 = Wd[(kb_+1)*DIi + col0 + s_bn];                           \
                     rb2 = Wd[(kb_+2)*DIi + col0 + s_bn];                           \
                     rb3 = Wd[(kb_+3)*DIi + col0 + s_bn];                           \
                     rb4 = Wd[(kb_+4)*DIi + col0 + s_bn];                           \
                     rb5 = Wd[(kb_+5)*DIi + col0 + s_bn];                           \
                     rb6 = Wd[(kb_+6)*DIi + col0 + s_bn];                           \
                     rb7 = Wd[(kb_+7)*DIi + col0 + s_bn]; }
  TC_BODY_H(RR);
#undef LOADA
#undef LOADB
  #pragma unroll
  for (int mt=0;mt<2;mt++)
    #pragma unroll
    for (int nt=0;nt<4;nt++){
      int r = row0 + wm*32 + mt*16 + (lane>>2);
      int c = col0 + wn*32 + nt*8 + (lane&3)*2;
      float b0 = bd[c], b1 = bd[c+1];
      *(unsigned*)&g_delta[(size_t)r*DIi + c] =
          h2pack(spf(acc[mt][nt][0]+b0), spf(acc[mt][nt][1]+b1));
      *(unsigned*)&g_delta[(size_t)(r+8)*DIi + c] =
          h2pack(spf(acc[mt][nt][2]+b0), spf(acc[mt][nt][3]+b1));
    }
}

// out_proj: yg[8192,512](half) @ out_w[512,256] + residual (in place on g_res)
__global__ void __launch_bounds__(256,3)
k_gemm_out(const float* __restrict__ W0, const float* __restrict__ W1){
  int col0 = blockIdx.x*64, row0 = blockIdx.y*128;
  int half = row0 >> 12;
  const float* W = half ? W1 : W0;
  TC_DECL();
#define LOADA(k0_) { const __half* ap = &g_yg[(size_t)(row0+s_r)*DIi + (k0_)+s_kh*16]; \
                     raH0 = *(const uint4*)ap; raH1 = *(const uint4*)(ap+8); }
#define LOADB(k0_) { int kb_ = (k0_) + s_bq*8;                                     \
                     rb0 = W[(kb_+0)*DMm + col0 + s_bn];                           \
                     rb1 = W[(kb_+1)*DMm + col0 + s_bn];                           \
                     rb2 = W[(kb_+2)*DMm + col0 + s_bn];                           \
                     rb3 = W[(kb_+3)*DMm + col0 + s_bn];                           \
                     rb4 = W[(kb_+4)*DMm + col0 + s_bn];                           \
                     rb5 = W[(kb_+5)*DMm + col0 + s_bn];                           \
                     rb6 = W[(kb_+6)*DMm + col0 + s_bn];                           \
                     rb7 = W[(kb_+7)*DMm + col0 + s_bn]; }
  TC_BODY_H(DIi);
#undef LOADA
#undef LOADB
  #pragma unroll
  for (int mt=0;mt<2;mt++)
    #pragma unroll
    for (int nt=0;nt<4;nt++){
      int r = row0 + wm*32 + mt*16 + (lane>>2);
      int c = col0 + wn*32 + nt*8 + (lane&3)*2;
      float2 o0 = *(const float2*)&g_res[(size_t)r*DMm + c];
      float2 o1 = *(const float2*)&g_res[(size_t)(r+8)*DMm + c];
      *(float2*)&g_res[(size_t)r*DMm + c] =
          make_float2(acc[mt][nt][0]+o0.x, acc[mt][nt][1]+o0.y);
      *(float2*)&g_res[(size_t)(r+8)*DMm + c] =
          make_float2(acc[mt][nt][2]+o1.x, acc[mt][nt][3]+o1.y);
    }
}

// merge: concat(res_half0, res_half1_reversed)[4096,512] @ merge_w[512,256] -> out
__global__ void __launch_bounds__(256,3)
k_merge(const float* __restrict__ W, float* __restrict__ out){
  int col0 = blockIdx.x*64, row0 = blockIdx.y*128;
  TC_DECL();
  int r_ = row0 + s_r;
  int b_ = r_ >> 11, s_ = r_ & (Ss-1);
  int rrev = MM + b_*Ss + (Ss-1-s_);
#define LOADA(k0_) { int kk_ = (k0_)+s_kh*16;                                      \
    const float* pa = (kk_ < DMm) ? (g_res + (size_t)r_*DMm + kk_)                 \
                                  : (g_res + (size_t)rrev*DMm + kk_-DMm);          \
    raA0 = *(const float4*)pa;                                                     \
    raA1 = *(const float4*)(pa+4);                                                 \
    raA2 = *(const float4*)(pa+8);                                                 \
    raA3 = *(const float4*)(pa+12); }
#define LOADB(k0_) { int kb_ = (k0_) + s_bq*8;                                     \
                     rb0 = W[(kb_+0)*DMm + col0 + s_bn];                           \
                     rb1 = W[(kb_+1)*DMm + col0 + s_bn];                           \
                     rb2 = W[(kb_+2)*DMm + col0 + s_bn];                           \
                     rb3 = W[(kb_+3)*DMm + col0 + s_bn];                           \
                     rb4 = W[(kb_+4)*DMm + col0 + s_bn];                           \
                     rb5 = W[(kb_+5)*DMm + col0 + s_bn];                           \
                     rb6 = W[(kb_+6)*DMm + col0 + s_bn];                           \
                     rb7 = W[(kb_+7)*DMm + col0 + s_bn]; }
  TC_BODY(2*DMm);
#undef LOADA
#undef LOADB
  #pragma unroll
  for (int mt=0;mt<2;mt++)
    #pragma unroll
    for (int nt=0;nt<4;nt++){
      int r = row0 + wm*32 + mt*16 + (lane>>2);
      int c = col0 + wn*32 + nt*8 + (lane&3)*2;
      *(float2*)&out[(size_t)r*DMm + c]     = make_float2(acc[mt][nt][0], acc[mt][nt][1]);
      *(float2*)&out[(size_t)(r+8)*DMm + c] = make_float2(acc[mt][nt][2], acc[mt][nt][3]);
    }
}

// ---------------- causal depthwise conv (K=4) + silu, half I/O ----------------
__global__ void k_conv(const float* __restrict__ cw0, const float* __restrict__ cb0,
                       const float* __restrict__ cw1, const float* __restrict__ cb1){
  int idx = blockIdx.x*256 + threadIdx.x;   // (M2/4)*128
  int d4 = idx & 127, g = idx >> 7;         // g in [0, M2/4)
  int b2 = g >> 9, sg = g & 511;            // seq 0..3, group within seq
  int half = b2 >> 1;
  const float* cw = half ? cw1 : cw0;
  const float* cb = half ? cb1 : cb0;
  int m0 = b2*Ss + sg*4;
  int d = d4*4;
  float4 w0 = *(const float4*)(cw + (d+0)*4);
  float4 w1 = *(const float4*)(cw + (d+1)*4);
  float4 w2 = *(const float4*)(cw + (d+2)*4);
  float4 w3 = *(const float4*)(cw + (d+3)*4);
  float4 bv = *(const float4*)(cb + d);
  float4 x0, x1, x2;
  if (sg > 0){
    x0 = h4load(&g_xs[(size_t)(m0-3)*DIi + d]);
    x1 = h4load(&g_xs[(size_t)(m0-2)*DIi + d]);
    x2 = h4load(&g_xs[(size_t)(m0-1)*DIi + d]);
  } else {
    x0 = x1 = x2 = make_float4(0.f,0.f,0.f,0.f);
  }
  #pragma unroll
  for (int s=0;s<4;s++){
    float4 x3 = h4load(&g_xs[(size_t)(m0+s)*DIi + d]);
    float4 a;
    a.x = bv.x + w0.x*x0.x + w0.y*x1.x + w0.z*x2.x + w0.w*x3.x;
    a.y = bv.y + w1.x*x0.y + w1.y*x1.y + w1.z*x2.y + w1.w*x3.y;
    a.z = bv.z + w2.x*x0.z + w2.y*x1.z + w2.z*x2.z + w2.w*x3.z;
    a.w = bv.w + w3.x*x0.w + w3.y*x1.w + w3.z*x2.w + w3.w*x3.w;
    a.x = siluf(a.x); a.y = siluf(a.y); a.z = siluf(a.z); a.w = siluf(a.w);
    h4store(&g_xc[(size_t)(m0+s)*DIi + d], a);
    x0 = x1; x1 = x2; x2 = x3;
  }
}

// dA helper: if A[n] == -(n+1) (the actual dataset), dA_n = r^(n+1) with
// r = exp(-delta): 1 MUFU + 15 FMUL instead of 16 MUFU.
__device__ __forceinline__ void dA_compute(float* dAv, const float* A,
                                           float dlt, bool fast){
  if (fast){
    float r = __expf(-dlt);
    dAv[0] = r; dAv[1] = r*r;
    #pragma unroll
    for (int n=2;n<NN;n++) dAv[n] = dAv[n>>1]*dAv[(n-1)>>1];
  } else {
    #pragma unroll
    for (int n=0;n<NN;n++) dAv[n] = __expf(dlt*A[n]);
  }
}

__device__ __forceinline__ bool a_fast(const float* A){
  bool f = true;
  #pragma unroll
  for (int n=0;n<NN;n++) f = f && (fabsf(A[n] + (float)(n+1)) < 1e-5f*(n+1));
  return f;
}

// ---------------- chunked scan phase 1 ----------------
__global__ void k_scan1(const float* __restrict__ Alog0, const float* __restrict__ Alog1){
  __shared__ float sB[CHUNK][NN];
  int blk = blockIdx.x;               // 2 * NSEQ*NCH = 512
  int bc_ = blk >> 1;                 // 0..255
  int seq = bc_ >> 6, c = bc_ & 63;
  int half = seq >> 1;
  const float* Alog = half ? Alog1 : Alog0;
  int d = (blk & 1)*256 + threadIdx.x;
  int m0 = seq*Ss + c*CHUNK;
  { int i0 = threadIdx.x, i1 = threadIdx.x + 256;
    sB[i0>>4][i0&15] = g_proj[(size_t)(m0+(i0>>4))*64 + 32 + (i0&15)];
    sB[i1>>4][i1&15] = g_proj[(size_t)(m0+(i1>>4))*64 + 32 + (i1&15)]; }
  float A[NN];
  #pragma unroll
  for (int n=0;n<NN;n++) A[n] = -__expf(Alog[d*NN + n]);
  bool fast = a_fast(A);
  __syncthreads();
  float h[NN];
  #pragma unroll
  for (int n=0;n<NN;n++) h[n] = 0.f;
  float sd = 0.f;
  #pragma unroll 1
  for (int s=0;s<CHUNK;s++){
    size_t m = m0 + s;
    float dlt = __half2float(g_delta[m*DIi + d]);
    float dx  = dlt * __half2float(g_xc[m*DIi + d]);
    sd += dlt;
    float dAv[NN];
    dA_compute(dAv, A, dlt, fast);
    #pragma unroll
    for (int n=0;n<NN;n++) h[n] = dAv[n]*h[n] + dx*sB[s][n];
  }
  size_t base = ((size_t)bc_*DIi + d)*NN;
  float Pv[NN];
  dA_compute(Pv, A, sd, fast);
  #pragma unroll
  for (int n=0;n<NN;n++){ g_Q[base+n]=h[n]; g_P[base+n]=Pv[n]; }
}

// ---------------- phase 2: combine across chunks ----------------
__global__ void k_comb(){
  int i = blockIdx.x*128 + threadIdx.x;     // NSEQ*DIi*NN = 32768
  int n = i & 15, d = (i >> 4) & (DIi-1), seq = i >> 13;
  float H = 0.f;
  for (int c=0;c<NCH;c++){
    size_t idx = (((size_t)(seq*NCH+c))*DIi + d)*NN + n;
    g_Hin[idx] = H;
    H = g_P[idx]*H + g_Q[idx];
  }
}

// ---------------- phase 3: replay + gated output ----------------
__global__ void k_scan2(const float* __restrict__ Alog0, const float* __restrict__ Alog1,
                        const float* __restrict__ Dp0, const float* __restrict__ Dp1){
  __shared__ float sB[CHUNK][NN];
  __shared__ float sC[CHUNK][NN];
  int blk = blockIdx.x;
  int bc_ = blk >> 1;
  int seq = bc_ >> 6, c = bc_ & 63;
  int half = seq >> 1;
  const float* Alog = half ? Alog1 : Alog0;
  const float* Dp   = half ? Dp1   : Dp0;
  int d = (blk & 1)*256 + threadIdx.x;
  int m0 = seq*Ss + c*CHUNK;
  { int i0 = threadIdx.x, i1 = threadIdx.x + 256;
    sB[i0>>4][i0&15] = g_proj[(size_t)(m0+(i0>>4))*64 + 32 + (i0&15)];
    sB[i1>>4][i1&15] = g_proj[(size_t)(m0+(i1>>4))*64 + 32 + (i1&15)];
    sC[i0>>4][i0&15] = g_proj[(size_t)(m0+(i0>>4))*64 + 48 + (i0&15)];
    sC[i1>>4][i1&15] = g_proj[(size_t)(m0+(i1>>4))*64 + 48 + (i1&15)]; }
  float A[NN];
  #pragma unroll
  for (int n=0;n<NN;n++) A[n] = -__expf(Alog[d*NN + n]);
  bool fast = a_fast(A);
  float h[NN];
  size_t base = ((size_t)bc_*DIi + d)*NN;
  #pragma unroll
  for (int n=0;n<NN;n++) h[n] = g_Hin[base+n];
  float Dv = Dp[d];
  __syncthreads();
  #pragma unroll 1
  for (int s=0;s<CHUNK;s++){
    size_t m = m0 + s;
    float dlt = __half2float(g_delta[m*DIi + d]);
    float x   = __half2float(g_xc[m*DIi + d]);
    float dx  = dlt * x;
    float dAv[NN];
    dA_compute(dAv, A, dlt, fast);
    float y = 0.f;
    #pragma unroll
    for (int n=0;n<NN;n++){
      h[n] = dAv[n]*h[n] + dx*sB[s][n];
      y += h[n]*sC[s][n];
    }
    y += Dv*x;
    float zv = __half2float(g_z[m*DIi + d]);
    g_yg[m*DIi + d] = __float2half(y * siluf(zv));
  }
}

// ---------------- driver ----------------
extern "C" void kernel_launch(void* const* d_in, const int* in_sizes, int n_in,
                              void* d_out, int out_size){
  const float* x      = (const float*)d_in[0];
  const float* in_w   = (const float*)d_in[1];
  const float* conv_w = (const float*)d_in[2];
  const float* conv_b = (const float*)d_in[3];
  const float* A_log  = (const float*)d_in[4];
  const float* xd_w   = (const float*)d_in[5];
  const float* xB_w   = (const float*)d_in[6];
  const float* xC_w   = (const float*)d_in[7];
  const float* dtp_w  = (const float*)d_in[8];
  const float* dtp_b  = (const float*)d_in[9];
  const float* Dp     = (const float*)d_in[10];
  const float* out_w  = (const float*)d_in[11];
  const float* ln_g   = (const float*)d_in[12];
  const float* ln_b   = (const float*)d_in[13];
  const float* merge_w= (const float*)d_in[14];
  float* out = (float*)d_out;

  k_init<<<M2*64/256, 256>>>(x);
  for (int bi=0; bi<2; bi++){
    int b0 = bi, b1 = 2 + bi;
    k_gemm_in <<<dim3(16,64), 256>>>(in_w + (size_t)b0*DMm*2*DIi,
                                     in_w + (size_t)b1*DMm*2*DIi,
                                     ln_g + b0*DMm, ln_b + b0*DMm,
                                     ln_g + b1*DMm, ln_b + b1*DMm);
    k_conv    <<<(M2/4)*128/256, 256>>>(conv_w + b0*DIi*4, conv_b + b0*DIi,
                                        conv_w + b1*DIi*4, conv_b + b1*DIi);
    k_gemm_x  <<<dim3(KS,64), 256>>>(xd_w + b0*DIi*RR, xB_w + b0*DIi*NN, xC_w + b0*DIi*NN,
                                     xd_w + b1*DIi*RR, xB_w + b1*DIi*NN, xC_w + b1*DIi*NN);
    k_xred    <<<M2*16/256, 256>>>();
    k_gemm_dt <<<dim3(8,64), 256>>>(dtp_w + b0*RR*DIi, dtp_b + b0*DIi,
                                    dtp_w + b1*RR*DIi, dtp_b + b1*DIi);
    k_scan1   <<<2*NSEQ*NCH, 256>>>(A_log + b0*DIi*NN, A_log + b1*DIi*NN);
    k_comb    <<<256, 128>>>();
    k_scan2   <<<2*NSEQ*NCH, 256>>>(A_log + b0*DIi*NN, A_log + b1*DIi*NN,
                                    Dp + b0*DIi, Dp + b1*DIi);
    k_gemm_out<<<dim3(4,64), 256>>>(out_w + (size_t)b0*DIi*DMm,
                                    out_w + (size_t)b1*DIi*DMm);
  }
  k_merge<<<dim3(4,32), 256>>>(merge_w, out);
}

// round 10
// speedup vs baseline: 1.1780x; 1.1780x over previous
#include <cuda_runtime.h>
#include <cuda_fp16.h>

// ---------------- problem constants ----------------
#define Bb   2
#define Ss   2048
#define DMm  256
#define DIi  512
#define NN   16
#define RR   32
#define MM   (Bb*Ss)          // 4096 rows per chain
#define M2   (2*MM)           // 8192 rows: [fwd | reversed]
#define CHUNK 32
#define NCH  (Ss/CHUNK)       // 64 chunks per sequence
#define NSEQ 4                // 4 sequences total (2 fwd + 2 rev)
#define KS   4                // split-K for x-proj
#define PSTR ((size_t)M2*64)  // projp partial stride

// ---------------- device scratch ----------------
__device__ float  g_res [M2*DMm];
__device__ __half g_xs  [M2*DIi];
__device__ __half g_z   [M2*DIi];
__device__ __half g_xc  [M2*DIi];
__device__ float  g_projp[KS*M2*64];      // split-K partials (fp32)
__device__ __half g_delta[M2*DIi];
__device__ __half g_yg  [M2*DIi];
__device__ float  g_P   [NSEQ*NCH*DIi*NN];
__device__ float  g_Q   [NSEQ*NCH*DIi*NN];
__device__ float  g_Hin [NSEQ*NCH*DIi*NN];

__device__ __forceinline__ float siluf(float x){ return x / (1.f + __expf(-x)); }
__device__ __forceinline__ float spf(float a){ return (a > 20.f) ? a : log1pf(__expf(a)); }

__device__ __forceinline__ unsigned h2pack(float a, float b){
  __half2 h = __floats2half2_rn(a, b);
  return *reinterpret_cast<unsigned*>(&h);
}
__device__ __forceinline__ float4 h4load(const __half* p){
  uint2 u = *(const uint2*)p;
  float2 fa = __half22float2(*(__half2*)&u.x);
  float2 fb = __half22float2(*(__half2*)&u.y);
  return make_float4(fa.x, fa.y, fb.x, fb.y);
}
__device__ __forceinline__ void h4store(__half* p, float4 v){
  uint2 u; u.x = h2pack(v.x, v.y); u.y = h2pack(v.z, v.w);
  *(uint2*)p = u;
}
// 4-way split-K partial sum at offset o (in elements of one partial)
__device__ __forceinline__ float psum(size_t o){
  return g_projp[o] + g_projp[PSTR + o] + g_projp[2*PSTR + o] + g_projp[3*PSTR + o];
}

#define MMA16(c, a, b)                                                       \
  asm volatile("mma.sync.aligned.m16n8k16.row.col.f32.f16.f16.f32 "          \
               "{%0,%1,%2,%3},{%4,%5,%6,%7},{%8,%9},{%0,%1,%2,%3};"          \
               : "+f"((c)[0]), "+f"((c)[1]), "+f"((c)[2]), "+f"((c)[3])      \
               : "r"((a)[0]), "r"((a)[1]), "r"((a)[2]), "r"((a)[3]),         \
                 "r"((b)[0]), "r"((b)[1]))

// ---------------- init: fwd + reversed copies ----------------
__global__ void k_init(const float* __restrict__ x){
  int idx = blockIdx.x*256 + threadIdx.x;       // M2*64 float4s
  int col = idx & 63;
  int m   = idx >> 6;                           // 0..8191
  int half = m >> 12;
  int b = (m >> 11) & 1, s = m & (Ss-1);
  int ms = b*Ss + (half ? (Ss-1-s) : s);
  reinterpret_cast<float4*>(g_res)[m*64+col] =
      reinterpret_cast<const float4*>(x)[ms*64+col];
}

// ======================================================================
// FP16 tensor-core GEMM core, double-buffered, mma.m16n8k16.
// Block tile 128(M) x 64(N), 256 threads = 8 warps (4 M x 2 N),
// warp tile 32x32. K-chunk = 16 = one mma k-step.  (round-7 proven core)
// Fragments per-lane contiguous -> LDS.128/LDS.64 conflict-free.
// ======================================================================
#define TC_DECL()                                                     \
  __shared__ __align__(16) unsigned Af[2][1024];                      \
  __shared__ __align__(16) unsigned Bf[2][512];                       \
  const int t = threadIdx.x;                                          \
  const int lane = t & 31, wid = t >> 5;                              \
  const int wm = wid >> 1, wn = wid & 1;                              \
  const int s_r  = t >> 1;          /* A staging row 0..127  */       \
  const int s_kb = (t & 1) * 8;     /* A staging k base 0/8  */       \
  const int s_bq = t >> 6;          /* B staging k-quad 0..3 */       \
  const int s_bn = t & 63;          /* B staging n 0..63     */       \
  float acc[2][4][4] = {};                                            \
  float4 raA0, raA1; uint4 raH;                                       \
  float rb0, rb1, rb2, rb3;                                           \
  (void)raA0; (void)raA1; (void)raH;

#define TC_AB(buf) &Af[buf][(((s_r>>4)*32 + ((s_r&7)*4))*4) + ((s_r>>3)&1) + ((s_kb>>2)&2)]

#define TC_STAGE_B(buf) {                                             \
  int ln0 = (s_bn & 7)*4 + ((2*s_bq) & 3);                            \
  int rgB = s_bq >> 1;                                                \
  unsigned* bb = &Bf[buf][((s_bn >> 3)*32 + ln0)*2 + rgB];            \
  bb[0] = h2pack(rb0, rb1);                                           \
  bb[2] = h2pack(rb2, rb3); }

#define TC_STAGE_F(buf) {                                             \
  unsigned* ab = TC_AB(buf);                                          \
  ab[0]  = h2pack(raA0.x, raA0.y);                                    \
  ab[4]  = h2pack(raA0.z, raA0.w);                                    \
  ab[8]  = h2pack(raA1.x, raA1.y);                                    \
  ab[12] = h2pack(raA1.z, raA1.w);                                    \
  TC_STAGE_B(buf) }

#define TC_STAGE_H(buf) {                                             \
  unsigned* ab = TC_AB(buf);                                          \
  ab[0]  = raH.x;                                                     \
  ab[4]  = raH.y;                                                     \
  ab[8]  = raH.z;                                                     \
  ab[12] = raH.w;                                                     \
  TC_STAGE_B(buf) }

#define TC_COMP(buf) {                                                \
  unsigned a_[2][4]; unsigned b_[4][2];                               \
  _Pragma("unroll") for (int mt=0;mt<2;mt++)                          \
    *(uint4*)a_[mt] = *(const uint4*)&Af[buf][((wm*2+mt)*32 + lane)*4]; \
  _Pragma("unroll") for (int nt=0;nt<4;nt++)                          \
    *(uint2*)b_[nt] = *(const uint2*)&Bf[buf][((wn*4+nt)*32 + lane)*2]; \
  _Pragma("unroll") for (int mt=0;mt<2;mt++)                          \
    _Pragma("unroll") for (int nt=0;nt<4;nt++)                        \
      MMA16(acc[mt][nt], a_[mt], b_[nt]); }

#define TC_BODY_GEN(KT, STG)                                          \
  LOADA(0); LOADB(0);                                                 \
  STG(0);                                                             \
  if (16 < (KT)) { LOADA(16); LOADB(16); }                            \
  __syncthreads();                                                    \
  { int cur = 0;                                                      \
    _Pragma("unroll 1")                                               \
    for (int k0=0; k0<(KT); k0+=16){                                  \
      if (k0+16 < (KT)) STG(cur^1);                                   \
      if (k0+32 < (KT)) { LOADA(k0+32); LOADB(k0+32); }               \
      TC_COMP(cur);                                                   \
      __syncthreads();                                                \
      cur ^= 1;                                                       \
    } }

#define TC_BODY(KT)   TC_BODY_GEN(KT, TC_STAGE_F)
#define TC_BODY_H(KT) TC_BODY_GEN(KT, TC_STAGE_H)

// in_proj with fused LayerNorm:
//   LN(g_res)[8192,256] @ in_w[256,1024] -> xs | z (half)   per-half weights
__global__ void k_gemm_in(const float* __restrict__ W0, const float* __restrict__ W1,
                          const float* __restrict__ g0, const float* __restrict__ bt0,
                          const float* __restrict__ g1, const float* __restrict__ bt1){
  int col0 = blockIdx.x*64, row0 = blockIdx.y*128;
  int half = row0 >> 12;
  const float* W  = half ? W1  : W0;
  const float* gm = half ? g1  : g0;
  const float* bb = half ? bt1 : bt0;
  __shared__ float sG[DMm], sBt[DMm];
  TC_DECL();
  sG[t] = gm[t]; sBt[t] = bb[t];
  const float* rowp = g_res + (size_t)(row0 + s_r)*DMm;
  float sum = 0.f, sq = 0.f;
  #pragma unroll
  for (int j=0;j<16;j++){
    float4 v0 = *(const float4*)&rowp[j*16 + s_kb];
    float4 v1 = *(const float4*)&rowp[j*16 + s_kb + 4];
    sum += v0.x+v0.y+v0.z+v0.w + v1.x+v1.y+v1.z+v1.w;
    sq  += v0.x*v0.x+v0.y*v0.y+v0.z*v0.z+v0.w*v0.w
         + v1.x*v1.x+v1.y*v1.y+v1.z*v1.z+v1.w*v1.w;
  }
  sum += __shfl_xor_sync(~0u, sum, 1);
  sq  += __shfl_xor_sync(~0u, sq, 1);
  float mean = sum*(1.f/DMm);
  float rstd = rsqrtf(sq*(1.f/DMm) - mean*mean + 1e-5f);
  __syncthreads();   // sG/sBt visible
#define LOADA(k0_) { int kk_=(k0_)+s_kb;                                           \
    raA0 = *(const float4*)&rowp[kk_];                                             \
    raA1 = *(const float4*)&rowp[kk_+4];                                           \
    raA0.x=(raA0.x-mean)*rstd*sG[kk_+0]+sBt[kk_+0];                                \
    raA0.y=(raA0.y-mean)*rstd*sG[kk_+1]+sBt[kk_+1];                                \
    raA0.z=(raA0.z-mean)*rstd*sG[kk_+2]+sBt[kk_+2];                                \
    raA0.w=(raA0.w-mean)*rstd*sG[kk_+3]+sBt[kk_+3];                                \
    raA1.x=(raA1.x-mean)*rstd*sG[kk_+4]+sBt[kk_+4];                                \
    raA1.y=(raA1.y-mean)*rstd*sG[kk_+5]+sBt[kk_+5];                                \
    raA1.z=(raA1.z-mean)*rstd*sG[kk_+6]+sBt[kk_+6];                                \
    raA1.w=(raA1.w-mean)*rstd*sG[kk_+7]+sBt[kk_+7]; }
#define LOADB(k0_) { int kb_ = (k0_) + s_bq*4;                                     \
                     rb0 = W[(size_t)(kb_+0)*(2*DIi) + col0 + s_bn];               \
                     rb1 = W[(size_t)(kb_+1)*(2*DIi) + col0 + s_bn];               \
                     rb2 = W[(size_t)(kb_+2)*(2*DIi) + col0 + s_bn];               \
                     rb3 = W[(size_t)(kb_+3)*(2*DIi) + col0 + s_bn]; }
  TC_BODY(DMm);
#undef LOADA
#undef LOADB
  __half* dst = (col0 < DIi) ? g_xs : g_z;
  int cb = (col0 < DIi) ? col0 : col0 - DIi;
  #pragma unroll
  for (int mt=0;mt<2;mt++)
    #pragma unroll
    for (int nt=0;nt<4;nt++){
      int r = row0 + wm*32 + mt*16 + (lane>>2);
      int c = cb + wn*32 + nt*8 + (lane&3)*2;
      *(unsigned*)&dst[(size_t)r*DIi + c]     = h2pack(acc[mt][nt][0], acc[mt][nt][1]);
      *(unsigned*)&dst[(size_t)(r+8)*DIi + c] = h2pack(acc[mt][nt][2], acc[mt][nt][3]);
    }
}

// x-proj split-K: xc[8192,512](half) @ [xd(32)|xB(16)|xC(16)] -> projp[kz] (fp32)
__global__ void __launch_bounds__(256,4)
k_gemm_x(const float* __restrict__ xdw0, const float* __restrict__ xbw0,
         const float* __restrict__ xcw0,
         const float* __restrict__ xdw1, const float* __restrict__ xbw1,
         const float* __restrict__ xcw1){
  int kz = blockIdx.x, row0 = blockIdx.y*128;
  int half = row0 >> 12;
  int kbase = kz*(DIi/KS);
  TC_DECL();
  const float* bsrc; int ldb, boff;
  if      (s_bn < 32){ bsrc = half?xdw1:xdw0; ldb = 32; boff = s_bn;      }
  else if (s_bn < 48){ bsrc = half?xbw1:xbw0; ldb = 16; boff = s_bn - 32; }
  else               { bsrc = half?xcw1:xcw0; ldb = 16; boff = s_bn - 48; }
#define LOADA(k0_) { raH = *(const uint4*)&g_xc[(size_t)(row0+s_r)*DIi + kbase+(k0_)+s_kb]; }
#define LOADB(k0_) { int kb_ = kbase + (k0_) + s_bq*4;                                   \
                     rb0 = bsrc[(kb_+0)*ldb + boff];                                     \
                     rb1 = bsrc[(kb_+1)*ldb + boff];                                     \
                     rb2 = bsrc[(kb_+2)*ldb + boff];                                     \
                     rb3 = bsrc[(kb_+3)*ldb + boff]; }
  TC_BODY_H(DIi/KS);
#undef LOADA
#undef LOADB
  float* dst = g_projp + (size_t)kz*PSTR;
  #pragma unroll
  for (int mt=0;mt<2;mt++)
    #pragma unroll
    for (int nt=0;nt<4;nt++){
      int r = row0 + wm*32 + mt*16 + (lane>>2);
      int c = wn*32 + nt*8 + (lane&3)*2;
      *(float2*)&dst[(size_t)r*64 + c]     = make_float2(acc[mt][nt][0], acc[mt][nt][1]);
      *(float2*)&dst[(size_t)(r+8)*64 + c] = make_float2(acc[mt][nt][2], acc[mt][nt][3]);
    }
}

// delta: softplus(sumK(projp)[:, :32] @ dtp_w[32,512] + dtp_b) -> g_delta (half)
// split-K reduction folded into the A-load (K = 32, two chunks only).
__global__ void k_gemm_dt(const float* __restrict__ Wd0, const float* __restrict__ bd0,
                          const float* __restrict__ Wd1, const float* __restrict__ bd1){
  int col0 = blockIdx.x*64, row0 = blockIdx.y*128;
  int half = row0 >> 12;
  const float* Wd = half ? Wd1 : Wd0;
  const float* bd = half ? bd1 : bd0;
  TC_DECL();
#define LOADA(k0_) { size_t ao = (size_t)(row0+s_r)*64 + (k0_)+s_kb;               \
    float4 p0 = *(const float4*)&g_projp[ao];                                      \
    float4 p1 = *(const float4*)&g_projp[PSTR + ao];                               \
    float4 p2 = *(const float4*)&g_projp[2*PSTR + ao];                             \
    float4 p3 = *(const float4*)&g_projp[3*PSTR + ao];                             \
    raA0 = make_float4(p0.x+p1.x+p2.x+p3.x, p0.y+p1.y+p2.y+p3.y,                   \
                       p0.z+p1.z+p2.z+p3.z, p0.w+p1.w+p2.w+p3.w);                  \
    p0 = *(const float4*)&g_projp[ao+4];                                           \
    p1 = *(const float4*)&g_projp[PSTR + ao+4];                                    \
    p2 = *(const float4*)&g_projp[2*PSTR + ao+4];                                  \
    p3 = *(const float4*)&g_projp[3*PSTR + ao+4];                                  \
    raA1 = make_float4(p0.x+p1.x+p2.x+p3.x, p0.y+p1.y+p2.y+p3.y,                   \
                       p0.z+p1.z+p2.z+p3.z, p0.w+p1.w+p2.w+p3.w); }
#define LOADB(k0_) { int kb_ = (k0_) + s_bq*4;                                      \
                     rb0 = Wd[(kb_+0)*DIi + col0 + s_bn];                           \
                     rb1 = Wd[(kb_+1)*DIi + col0 + s_bn];                           \
                     rb2 = Wd[(kb_+2)*DIi + col0 + s_bn];                           \
                     rb3 = Wd[(kb_+3)*DIi + col0 + s_bn]; }
  TC_BODY(RR);
#undef LOADA
#undef LOADB
  #pragma unroll
  for (int mt=0;mt<2;mt++)
    #pragma unroll
    for (int nt=0;nt<4;nt++){
      int r = row0 + wm*32 + mt*16 + (lane>>2);
      int c = col0 + wn*32 + nt*8 + (lane&3)*2;
      float b0 = bd[c], b1 = bd[c+1];
      *(unsigned*)&g_delta[(size_t)r*DIi + c] =
          h2pack(spf(acc[mt][nt][0]+b0), spf(acc[mt][nt][1]+b1));
      *(unsigned*)&g_delta[(size_t)(r+8)*DIi + c] =
          h2pack(spf(acc[mt][nt][2]+b0), spf(acc[mt][nt][3]+b1));
    }
}

// out_proj: yg[8192,512](half) @ out_w[512,256] + residual (in place on g_res)
__global__ void __launch_bounds__(256,4)
k_gemm_out(const float* __restrict__ W0, const float* __restrict__ W1){
  int col0 = blockIdx.x*64, row0 = blockIdx.y*128;
  int half = row0 >> 12;
  const float* W = half ? W1 : W0;
  TC_DECL();
#define LOADA(k0_) { raH = *(const uint4*)&g_yg[(size_t)(row0+s_r)*DIi + (k0_)+s_kb]; }
#define LOADB(k0_) { int kb_ = (k0_) + s_bq*4;                                     \
                     rb0 = W[(kb_+0)*DMm + col0 + s_bn];                           \
                     rb1 = W[(kb_+1)*DMm + col0 + s_bn];                           \
                     rb2 = W[(kb_+2)*DMm + col0 + s_bn];                           \
                     rb3 = W[(kb_+3)*DMm + col0 + s_bn]; }
  TC_BODY_H(DIi);
#undef LOADA
#undef LOADB
  #pragma unroll
  for (int mt=0;mt<2;mt++)
    #pragma unroll
    for (int nt=0;nt<4;nt++){
      int r = row0 + wm*32 + mt*16 + (lane>>2);
      int c = col0 + wn*32 + nt*8 + (lane&3)*2;
      float2 o0 = *(const float2*)&g_res[(size_t)r*DMm + c];
      float2 o1 = *(const float2*)&g_res[(size_t)(r+8)*DMm + c];
      *(float2*)&g_res[(size_t)r*DMm + c] =
          make_float2(acc[mt][nt][0]+o0.x, acc[mt][nt][1]+o0.y);
      *(float2*)&g_res[(size_t)(r+8)*DMm + c] =
          make_float2(acc[mt][nt][2]+o1.x, acc[mt][nt][3]+o1.y);
    }
}

// merge: concat(res_half0, res_half1_reversed)[4096,512] @ merge_w[512,256] -> out
__global__ void __launch_bounds__(256,4)
k_merge(const float* __restrict__ W, float* __restrict__ out){
  int col0 = blockIdx.x*64, row0 = blockIdx.y*128;
  TC_DECL();
  int r_ = row0 + s_r;
  int b_ = r_ >> 11, s_ = r_ & (Ss-1);
  int rrev = MM + b_*Ss + (Ss-1-s_);
#define LOADA(k0_) {                                                               \
    int kk0 = (k0_)+s_kb, kk1 = (k0_)+s_kb+4;                                      \
    raA0 = *(const float4*)((kk0 < DMm) ? (g_res + (size_t)r_*DMm + kk0)           \
                                        : (g_res + (size_t)rrev*DMm + kk0-DMm));   \
    raA1 = *(const float4*)((kk1 < DMm) ? (g_res + (size_t)r_*DMm + kk1)           \
                                        : (g_res + (size_t)rrev*DMm + kk1-DMm)); }
#define LOADB(k0_) { int kb_ = (k0_) + s_bq*4;                                     \
                     rb0 = W[(kb_+0)*DMm + col0 + s_bn];                           \
                     rb1 = W[(kb_+1)*DMm + col0 + s_bn];                           \
                     rb2 = W[(kb_+2)*DMm + col0 + s_bn];                           \
                     rb3 = W[(kb_+3)*DMm + col0 + s_bn]; }
  TC_BODY(2*DMm);
#undef LOADA
#undef LOADB
  #pragma unroll
  for (int mt=0;mt<2;mt++)
    #pragma unroll
    for (int nt=0;nt<4;nt++){
      int r = row0 + wm*32 + mt*16 + (lane>>2);
      int c = col0 + wn*32 + nt*8 + (lane&3)*2;
      *(float2*)&out[(size_t)r*DMm + c]     = make_float2(acc[mt][nt][0], acc[mt][nt][1]);
      *(float2*)&out[(size_t)(r+8)*DMm + c] = make_float2(acc[mt][nt][2], acc[mt][nt][3]);
    }
}

// ---------------- causal depthwise conv (K=4) + silu, half I/O ----------------
__global__ void k_conv(const float* __restrict__ cw0, const float* __restrict__ cb0,
                       const float* __restrict__ cw1, const float* __restrict__ cb1){
  int idx = blockIdx.x*256 + threadIdx.x;   // (M2/4)*128
  int d4 = idx & 127, g = idx >> 7;         // g in [0, M2/4)
  int b2 = g >> 9, sg = g & 511;            // seq 0..3, group within seq
  int half = b2 >> 1;
  const float* cw = half ? cw1 : cw0;
  const float* cb = half ? cb1 : cb0;
  int m0 = b2*Ss + sg*4;
  int d = d4*4;
  float4 w0 = *(const float4*)(cw + (d+0)*4);
  float4 w1 = *(const float4*)(cw + (d+1)*4);
  float4 w2 = *(const float4*)(cw + (d+2)*4);
  float4 w3 = *(const float4*)(cw + (d+3)*4);
  float4 bv = *(const float4*)(cb + d);
  float4 x0, x1, x2;
  if (sg > 0){
    x0 = h4load(&g_xs[(size_t)(m0-3)*DIi + d]);
    x1 = h4load(&g_xs[(size_t)(m0-2)*DIi + d]);
    x2 = h4load(&g_xs[(size_t)(m0-1)*DIi + d]);
  } else {
    x0 = x1 = x2 = make_float4(0.f,0.f,0.f,0.f);
  }
  #pragma unroll
  for (int s=0;s<4;s++){
    float4 x3 = h4load(&g_xs[(size_t)(m0+s)*DIi + d]);
    float4 a;
    a.x = bv.x + w0.x*x0.x + w0.y*x1.x + w0.z*x2.x + w0.w*x3.x;
    a.y = bv.y + w1.x*x0.y + w1.y*x1.y + w1.z*x2.y + w1.w*x3.y;
    a.z = bv.z + w2.x*x0.z + w2.y*x1.z + w2.z*x2.z + w2.w*x3.z;
    a.w = bv.w + w3.x*x0.w + w3.y*x1.w + w3.z*x2.w + w3.w*x3.w;
    a.x = siluf(a.x); a.y = siluf(a.y); a.z = siluf(a.z); a.w = siluf(a.w);
    h4store(&g_xc[(size_t)(m0+s)*DIi + d], a);
    x0 = x1; x1 = x2; x2 = x3;
  }
}

// dA helper: if A[n] == -(n+1) (the actual dataset), dA_n = r^(n+1) with
// r = exp(-delta): 1 MUFU + 15 FMUL instead of 16 MUFU.
__device__ __forceinline__ void dA_compute(float* dAv, const float* A,
                                           float dlt, bool fast){
  if (fast){
    float r = __expf(-dlt);
    dAv[0] = r; dAv[1] = r*r;
    #pragma unroll
    for (int n=2;n<NN;n++) dAv[n] = dAv[n>>1]*dAv[(n-1)>>1];
  } else {
    #pragma unroll
    for (int n=0;n<NN;n++) dAv[n] = __expf(dlt*A[n]);
  }
}

__device__ __forceinline__ bool a_fast(const float* A){
  bool f = true;
  #pragma unroll
  for (int n=0;n<NN;n++) f = f && (fabsf(A[n] + (float)(n+1)) < 1e-5f*(n+1));
  return f;
}

// ---------------- chunked scan phase 1 ----------------
__global__ void k_scan1(const float* __restrict__ Alog0, const float* __restrict__ Alog1){
  __shared__ float sB[CHUNK][NN];
  int blk = blockIdx.x;               // 2 * NSEQ*NCH = 512
  int bc_ = blk >> 1;                 // 0..255
  int seq = bc_ >> 6, c = bc_ & 63;
  int half = seq >> 1;
  const float* Alog = half ? Alog1 : Alog0;
  int d = (blk & 1)*256 + threadIdx.x;
  int m0 = seq*Ss + c*CHUNK;
  { int i0 = threadIdx.x, i1 = threadIdx.x + 256;
    size_t o0 = (size_t)(m0+(i0>>4))*64 + 32 + (i0&15);
    size_t o1 = (size_t)(m0+(i1>>4))*64 + 32 + (i1&15);
    sB[i0>>4][i0&15] = psum(o0);
    sB[i1>>4][i1&15] = psum(o1); }
  float A[NN];
  #pragma unroll
  for (int n=0;n<NN;n++) A[n] = -__expf(Alog[d*NN + n]);
  bool fast = a_fast(A);
  __syncthreads();
  float h[NN];
  #pragma unroll
  for (int n=0;n<NN;n++) h[n] = 0.f;
  float sd = 0.f;
  #pragma unroll 1
  for (int s=0;s<CHUNK;s++){
    size_t m = m0 + s;
    float dlt = __half2float(g_delta[m*DIi + d]);
    float dx  = dlt * __half2float(g_xc[m*DIi + d]);
    sd += dlt;
    float dAv[NN];
    dA_compute(dAv, A, dlt, fast);
    #pragma unroll
    for (int n=0;n<NN;n++) h[n] = dAv[n]*h[n] + dx*sB[s][n];
  }
  size_t base = ((size_t)bc_*DIi + d)*NN;
  float Pv[NN];
  dA_compute(Pv, A, sd, fast);
  #pragma unroll
  for (int n=0;n<NN;n++){ g_Q[base+n]=h[n]; g_P[base+n]=Pv[n]; }
}

// ---------------- phase 2: combine across chunks ----------------
__global__ void k_comb(){
  int i = blockIdx.x*128 + threadIdx.x;     // NSEQ*DIi*NN = 32768
  int n = i & 15, d = (i >> 4) & (DIi-1), seq = i >> 13;
  float H = 0.f;
  for (int c=0;c<NCH;c++){
    size_t idx = (((size_t)(seq*NCH+c))*DIi + d)*NN + n;
    g_Hin[idx] = H;
    H = g_P[idx]*H + g_Q[idx];
  }
}

// ---------------- phase 3: replay + gated output ----------------
__global__ void k_scan2(const float* __restrict__ Alog0, const float* __restrict__ Alog1,
                        const float* __restrict__ Dp0, const float* __restrict__ Dp1){
  __shared__ float sB[CHUNK][NN];
  __shared__ float sC[CHUNK][NN];
  int blk = blockIdx.x;
  int bc_ = blk >> 1;
  int seq = bc_ >> 6, c = bc_ & 63;
  int half = seq >> 1;
  const float* Alog = half ? Alog1 : Alog0;
  const float* Dp   = half ? Dp1   : Dp0;
  int d = (blk & 1)*256 + threadIdx.x;
  int m0 = seq*Ss + c*CHUNK;
  { int i0 = threadIdx.x, i1 = threadIdx.x + 256;
    size_t o0 = (size_t)(m0+(i0>>4))*64 + (i0&15);
    size_t o1 = (size_t)(m0+(i1>>4))*64 + (i1&15);
    sB[i0>>4][i0&15] = psum(o0 + 32);
    sB[i1>>4][i1&15] = psum(o1 + 32);
    sC[i0>>4][i0&15] = psum(o0 + 48);
    sC[i1>>4][i1&15] = psum(o1 + 48); }
  float A[NN];
  #pragma unroll
  for (int n=0;n<NN;n++) A[n] = -__expf(Alog[d*NN + n]);
  bool fast = a_fast(A);
  float h[NN];
  size_t base = ((size_t)bc_*DIi + d)*NN;
  #pragma unroll
  for (int n=0;n<NN;n++) h[n] = g_Hin[base+n];
  float Dv = Dp[d];
  __syncthreads();
  #pragma unroll 1
  for (int s=0;s<CHUNK;s++){
    size_t m = m0 + s;
    float dlt = __half2float(g_delta[m*DIi + d]);
    float x   = __half2float(g_xc[m*DIi + d]);
    float dx  = dlt * x;
    float dAv[NN];
    dA_compute(dAv, A, dlt, fast);
    float y = 0.f;
    #pragma unroll
    for (int n=0;n<NN;n++){
      h[n] = dAv[n]*h[n] + dx*sB[s][n];
      y += h[n]*sC[s][n];
    }
    y += Dv*x;
    float zv = __half2float(g_z[m*DIi + d]);
    g_yg[m*DIi + d] = __float2half(y * siluf(zv));
  }
}

// ---------------- driver ----------------
extern "C" void kernel_launch(void* const* d_in, const int* in_sizes, int n_in,
                              void* d_out, int out_size){
  const float* x      = (const float*)d_in[0];
  const float* in_w   = (const float*)d_in[1];
  const float* conv_w = (const float*)d_in[2];
  const float* conv_b = (const float*)d_in[3];
  const float* A_log  = (const float*)d_in[4];
  const float* xd_w   = (const float*)d_in[5];
  const float* xB_w   = (const float*)d_in[6];
  const float* xC_w   = (const float*)d_in[7];
  const float* dtp_w  = (const float*)d_in[8];
  const float* dtp_b  = (const float*)d_in[9];
  const float* Dp     = (const float*)d_in[10];
  const float* out_w  = (const float*)d_in[11];
  const float* ln_g   = (const float*)d_in[12];
  const float* ln_b   = (const float*)d_in[13];
  const float* merge_w= (const float*)d_in[14];
  float* out = (float*)d_out;

  k_init<<<M2*64/256, 256>>>(x);
  for (int bi=0; bi<2; bi++){
    int b0 = bi, b1 = 2 + bi;
    k_gemm_in <<<dim3(16,64), 256>>>(in_w + (size_t)b0*DMm*2*DIi,
                                     in_w + (size_t)b1*DMm*2*DIi,
                                     ln_g + b0*DMm, ln_b + b0*DMm,
                                     ln_g + b1*DMm, ln_b + b1*DMm);
    k_conv    <<<(M2/4)*128/256, 256>>>(conv_w + b0*DIi*4, conv_b + b0*DIi,
                                        conv_w + b1*DIi*4, conv_b + b1*DIi);
    k_gemm_x  <<<dim3(KS,64), 256>>>(xd_w + b0*DIi*RR, xB_w + b0*DIi*NN, xC_w + b0*DIi*NN,
                                     xd_w + b1*DIi*RR, xB_w + b1*DIi*NN, xC_w + b1*DIi*NN);
    k_gemm_dt <<<dim3(8,64), 256>>>(dtp_w + b0*RR*DIi, dtp_b + b0*DIi,
                                    dtp_w + b1*RR*DIi, dtp_b + b1*DIi);
    k_scan1   <<<2*NSEQ*NCH, 256>>>(A_log + b0*DIi*NN, A_log + b1*DIi*NN);
    k_comb    <<<256, 128>>>();
    k_scan2   <<<2*NSEQ*NCH, 256>>>(A_log + b0*DIi*NN, A_log + b1*DIi*NN,
                                    Dp + b0*DIi, Dp + b1*DIi);
    k_gemm_out<<<dim3(4,64), 256>>>(out_w + (size_t)b0*DIi*DMm,
                                    out_w + (size_t)b1*DIi*DMm);
  }
  k_merge<<<dim3(4,32), 256>>>(merge_w, out);
}